// round 10
// baseline (speedup 1.0000x reference)
#include <cuda_runtime.h>
#include <cstdint>

// Problem constants
#define NN 100000
#define EE 3200000
#define FIN 512
#define HH 16
#define CC 40

// ---------------- scratch (device globals, referenced DIRECTLY by kernels) --
__device__ float g_h0[NN * HH];
__device__ float g_h1[NN * HH];
__device__ float g_agg[NN * HH];
__device__ float g_deg[NN];
__device__ float g_dinv[NN];
__device__ int   g_cnt[NN];
__device__ int   g_offs[NN];
__device__ int   g_cur[NN];
__device__ int2  g_edge[EE];     // (src, nrm-bits) packed
__device__ int   g_total;

// ---------------- packed f32x2 helpers (PTX; sm_100+) -----------------------
__device__ __forceinline__ unsigned long long pack2(float v) {
    unsigned long long r;
    asm("mov.b64 %0, {%1,%1};" : "=l"(r) : "f"(v));
    return r;
}
__device__ __forceinline__ void fma2(unsigned long long& acc,
                                     unsigned long long a, unsigned long long b) {
    asm("fma.rn.f32x2 %0, %1, %2, %0;" : "+l"(acc) : "l"(a), "l"(b));
}
__device__ __forceinline__ void add2(unsigned long long& a, unsigned long long b) {
    asm("add.rn.f32x2 %0, %0, %1;" : "+l"(a) : "l"(b));
}
__device__ __forceinline__ float lo2(unsigned long long v) {
    return __uint_as_float((unsigned)(v & 0xffffffffu));
}
__device__ __forceinline__ float hi2(unsigned long long v) {
    return __uint_as_float((unsigned)(v >> 32));
}

// ---------------- fc1: g_h0 = relu(x @ W_first + b_first) -------------------
// warp-per-row; coalesced x loads; W smem stride 20 floats (80B, 8B-aligned).
#define FC1_WPB 8
#define WSTRIDE 20
__global__ void __launch_bounds__(FC1_WPB * 32)
k_fc1(const float* __restrict__ x, const float* __restrict__ W,
      const float* __restrict__ b) {
    __shared__ float Wsh[FIN * WSTRIDE];   // 40 KB
    for (int i = threadIdx.x; i < FIN * HH; i += FC1_WPB * 32) {
        int k = i >> 4, j = i & 15;
        Wsh[k * WSTRIDE + j] = W[i];
    }
    __syncthreads();

    int warp = threadIdx.x >> 5, lane = threadIdx.x & 31;
    int row = blockIdx.x * FC1_WPB + warp;
    if (row >= NN) return;
    const float* xr = x + (size_t)row * FIN;

    // coalesced: lane k0 = lane + 32t
    float xv[16];
#pragma unroll
    for (int t = 0; t < 16; t++) xv[t] = xr[lane + 32 * t];

    unsigned long long acc[8];
#pragma unroll
    for (int p = 0; p < 8; p++) acc[p] = 0ull;

#pragma unroll
    for (int t = 0; t < 16; t++) {
        int k = lane + 32 * t;
        unsigned long long px = pack2(xv[t]);
        const unsigned long long* wr = (const unsigned long long*)(Wsh + k * WSTRIDE);
#pragma unroll
        for (int p = 0; p < 8; p++) fma2(acc[p], px, wr[p]);
    }
    // warp tree-reduce packed pairs
#pragma unroll
    for (int p = 0; p < 8; p++) {
        unsigned long long v = acc[p];
#pragma unroll
        for (int s = 16; s > 0; s >>= 1) {
            unsigned long long o = __shfl_xor_sync(0xffffffffu, v, s);
            add2(v, o);
        }
        acc[p] = v;
    }
    if (lane == 0) {
        float of[16];
#pragma unroll
        for (int p = 0; p < 8; p++) { of[2 * p] = lo2(acc[p]); of[2 * p + 1] = hi2(acc[p]); }
        float4* dst = (float4*)(g_h0 + (size_t)row * HH);
#pragma unroll
        for (int q = 0; q < 4; q++)
            dst[q] = make_float4(
                fmaxf(of[4 * q + 0] + __ldg(&b[4 * q + 0]), 0.0f),
                fmaxf(of[4 * q + 1] + __ldg(&b[4 * q + 1]), 0.0f),
                fmaxf(of[4 * q + 2] + __ldg(&b[4 * q + 2]), 0.0f),
                fmaxf(of[4 * q + 3] + __ldg(&b[4 * q + 3]), 0.0f));
    }
}

// ---------------- init ------------------------------------------------------
__global__ void k_init() {
    int i = blockIdx.x * blockDim.x + threadIdx.x;
    if (i < NN) { g_deg[i] = 1.0f; g_cnt[i] = 0; }
    if (i == 0) g_total = 0;
}

// ---------------- degree + histogram (edge_index is int32) ------------------
__global__ void k_deg(const int* __restrict__ ei, const float* __restrict__ ew) {
    int e = blockIdx.x * blockDim.x + threadIdx.x;
    if (e < EE) {
        int c = ei[EE + e];  // row 1 = target
        atomicAdd(&g_deg[c], ew[e]);
        atomicAdd(&g_cnt[c], 1);
    }
}

// ---------------- CSC offsets (warp scan + global cursor) + dinv ------------
__global__ void k_offs_dinv() {
    int i = blockIdx.x * blockDim.x + threadIdx.x;
    int lane = threadIdx.x & 31;
    int c = (i < NN) ? g_cnt[i] : 0;
    int v = c;
#pragma unroll
    for (int s = 1; s < 32; s <<= 1) {
        int o = __shfl_up_sync(0xffffffffu, v, s);
        if (lane >= s) v += o;
    }
    int total = __shfl_sync(0xffffffffu, v, 31);
    int base = 0;
    if (lane == 0) base = atomicAdd(&g_total, total);
    base = __shfl_sync(0xffffffffu, base, 0);
    int off = base + v - c;
    if (i < NN) {
        g_offs[i] = off;
        g_cur[i] = off;
        g_dinv[i] = rsqrtf(g_deg[i]);
    }
}

// ---------------- place edges into CSC slots (packed 8B store) --------------
__global__ void k_place(const int* __restrict__ ei, const float* __restrict__ ew) {
    int e = blockIdx.x * blockDim.x + threadIdx.x;
    if (e >= EE) return;
    int r = ei[e];
    int c = ei[EE + e];
    int pos = atomicAdd(&g_cur[c], 1);
    float nrm = g_dinv[r] * ew[e] * g_dinv[c];
    g_edge[pos] = make_int2(r, __float_as_int(nrm));
}

// ---------------- fused gather + 16x16 linear epilogue ----------------------
// out_node = [relu]( (A_norm . h)_node @ W  [+ bias] )
// warp per node: lane = eg(8) * 4 + f(4); edge reads packed, h reads 4x16B.
__device__ __forceinline__ float* buf(int id) {
    return (id == 0) ? g_h0 : (id == 1) ? g_h1 : g_agg;
}

template <int IN, int OUT, bool BIAS_RELU>
__global__ void __launch_bounds__(256)
k_g(const float* __restrict__ W, const float* __restrict__ bias) {
    __shared__ float Wsh[HH * HH];
    __shared__ float bsh[HH];
    if (threadIdx.x < HH * HH) Wsh[threadIdx.x] = W[threadIdx.x];
    if (BIAS_RELU && threadIdx.x < HH) bsh[threadIdx.x] = bias[threadIdx.x];
    __syncthreads();

    int node = (blockIdx.x * blockDim.x + threadIdx.x) >> 5;
    if (node >= NN) return;
    int lane = threadIdx.x & 31;
    int eg = lane >> 2;   // 0..7
    int f  = lane & 3;    // float4 column 0..3
    int base = g_offs[node];
    int n = g_cnt[node];
    const float4* h = (const float4*)buf(IN);

    float ax = 0.0f, ay = 0.0f, az = 0.0f, aw = 0.0f;
    for (int i = eg; i < n; i += 8) {
        int2 e = g_edge[base + i];
        float w = __int_as_float(e.y);
        float4 t = h[(size_t)e.x * 4 + f];
        ax += t.x * w; ay += t.y * w; az += t.z * w; aw += t.w * w;
    }
    // reduce across the 8 edge groups -> every lane has full sums for its f
#pragma unroll
    for (int s = 4; s < 32; s <<= 1) {
        ax += __shfl_xor_sync(0xffffffffu, ax, s);
        ay += __shfl_xor_sync(0xffffffffu, ay, s);
        az += __shfl_xor_sync(0xffffffffu, az, s);
        aw += __shfl_xor_sync(0xffffffffu, aw, s);
    }
    // self loop (identical value added in every eg copy)
    {
        float d = g_dinv[node];
        float ws = d * d;
        float4 t = h[(size_t)node * 4 + f];
        ax += t.x * ws; ay += t.y * ws; az += t.z * ws; aw += t.w * ws;
    }
    // broadcast to full 16-vector: v[4q+m] lives in lane q (f=q, eg=0 copy)
    float v[16];
#pragma unroll
    for (int q = 0; q < 4; q++) {
        v[4 * q + 0] = __shfl_sync(0xffffffffu, ax, q);
        v[4 * q + 1] = __shfl_sync(0xffffffffu, ay, q);
        v[4 * q + 2] = __shfl_sync(0xffffffffu, az, q);
        v[4 * q + 3] = __shfl_sync(0xffffffffu, aw, q);
    }
    // epilogue matmul: lane f computes outputs 4f..4f+3
    float o0 = 0.0f, o1 = 0.0f, o2 = 0.0f, o3 = 0.0f;
#pragma unroll
    for (int k = 0; k < 16; k++) {
        const float4 w = ((const float4*)Wsh)[k * 4 + f];  // W[k][4f..4f+3]
        o0 += v[k] * w.x; o1 += v[k] * w.y; o2 += v[k] * w.z; o3 += v[k] * w.w;
    }
    if (BIAS_RELU) {
        o0 = fmaxf(o0 + bsh[4 * f + 0], 0.0f);
        o1 = fmaxf(o1 + bsh[4 * f + 1], 0.0f);
        o2 = fmaxf(o2 + bsh[4 * f + 2], 0.0f);
        o3 = fmaxf(o3 + bsh[4 * f + 3], 0.0f);
    }
    if (eg == 0) {
        ((float4*)buf(OUT))[(size_t)node * 4 + f] = make_float4(o0, o1, o2, o3);
    }
}

// ---------------- output layer: relu(g_agg+b2) @ W_out + b_out, log_softmax -
__global__ void k_out(const float* __restrict__ b2, const float* __restrict__ Wout,
                      const float* __restrict__ bout, float* __restrict__ out) {
    __shared__ float Wsh[HH * CC];
    __shared__ float bosh[CC];
    __shared__ float b2sh[HH];
    for (int i = threadIdx.x; i < HH * CC; i += blockDim.x) Wsh[i] = Wout[i];
    if (threadIdx.x < CC) bosh[threadIdx.x] = bout[threadIdx.x];
    if (threadIdx.x < HH) b2sh[threadIdx.x] = b2[threadIdx.x];
    __syncthreads();

    int r = blockIdx.x * blockDim.x + threadIdx.x;
    if (r >= NN) return;

    float v[16];
    const float4* ir = (const float4*)(g_agg + (size_t)r * HH);
#pragma unroll
    for (int q = 0; q < 4; q++) {
        float4 t = ir[q];
        v[4 * q] = t.x; v[4 * q + 1] = t.y; v[4 * q + 2] = t.z; v[4 * q + 3] = t.w;
    }
#pragma unroll
    for (int j = 0; j < 16; j++) v[j] = fmaxf(v[j] + b2sh[j], 0.0f);

    float lg[CC];
#pragma unroll
    for (int j = 0; j < CC; j++) lg[j] = bosh[j];
#pragma unroll
    for (int k = 0; k < 16; k++) {
        float vk = v[k];
        const float* wr = &Wsh[k * CC];
#pragma unroll
        for (int j = 0; j < CC; j++) lg[j] += vk * wr[j];
    }
    float m = lg[0];
#pragma unroll
    for (int j = 1; j < CC; j++) m = fmaxf(m, lg[j]);
    float s = 0.0f;
#pragma unroll
    for (int j = 0; j < CC; j++) s += __expf(lg[j] - m);
    float ls = __logf(s) + m;
    float* orow = out + (size_t)r * CC;
#pragma unroll
    for (int j = 0; j < CC; j++) orow[j] = lg[j] - ls;
}

// ---------------- launch: ONLY kernel launches, no other CUDA API -----------
extern "C" void kernel_launch(void* const* d_in, const int* in_sizes, int n_in,
                              void* d_out, int out_size) {
    const float* x       = (const float*)d_in[0];
    const int*   ei      = (const int*)d_in[1];     // int32 (2, E) row-major
    const float* ew      = (const float*)d_in[2];
    const float* W_first = (const float*)d_in[3];
    const float* b_first = (const float*)d_in[4];
    const float* W_c1    = (const float*)d_in[5];
    const float* b_c1    = (const float*)d_in[6];
    const float* W_c2    = (const float*)d_in[7];
    const float* b_c2    = (const float*)d_in[8];
    const float* W_out   = (const float*)d_in[9];
    const float* b_out   = (const float*)d_in[10];
    float* out = (float*)d_out;

    const int TB = 256;
    int gN = (NN + TB - 1) / TB;
    int gE = (EE + TB - 1) / TB;
    int gW = (NN * 32 + TB - 1) / TB;  // warp per node

    // CSC build (shared by both conv layers)
    k_init<<<gN, TB>>>();
    k_deg<<<gE, TB>>>(ei, ew);
    k_offs_dinv<<<gN, TB>>>();
    k_place<<<gE, TB>>>(ei, ew);

    // fc1 -> g_h0
    k_fc1<<<NN / FC1_WPB, FC1_WPB * 32>>>(x, W_first, b_first);

    // conv1 fused: g_h1 = relu((A . g_h0) @ W_c1 + b_c1)
    k_g<0, 1, true><<<gW, TB>>>(W_c1, b_c1);
    // conv2 fused (no relu/bias; k_out applies them): g_agg = (A . g_h1) @ W_c2
    k_g<1, 2, false><<<gW, TB>>>(W_c2, nullptr);

    // output layer
    k_out<<<gN, TB>>>(b_c2, W_out, b_out, out);
}